// round 6
// baseline (speedup 1.0000x reference)
#include <cuda_runtime.h>

// Problem constants
#define BATCH 8
#define CH    256          // channels
#define NT    1024         // tokens = 32*32
#define NH    4            // heads
#define HD    64           // head dim
#define QKV   768          // 3 * NH * HD

// Scratch (device globals — no allocation allowed)
__device__ float g_q [BATCH * NH * NT * HD];                 // [b][h][n][d]
__device__ float g_k [BATCH * NH * NT * HD];
__device__ float g_v [BATCH * NH * NT * HD];
__device__ float g_S [(size_t)BATCH * NH * NT * NT];         // [bh][i][j]  (128 MB)
__device__ float g_ao[BATCH * NT * CH];                      // [b][n][h*64+d]

// ---------------------------------------------------------------------------
// Kernel 1: QKV projection.
//   qkv[m, o] = sum_c x[b, c, n] * Wp[c, o] + bp[o],   m = b*1024 + n
// A is naturally [k][m] in gmem (x is channel-major) -> straight tile loads.
// Each 64-wide o-tile maps to exactly one (head, q/k/v) slot since 192 = 3*64.
// ---------------------------------------------------------------------------
__global__ void __launch_bounds__(256) qkv_proj_kernel(
    const float* __restrict__ x, const float* __restrict__ Wp,
    const float* __restrict__ bp)
{
    __shared__ float As[16 * 64];
    __shared__ float Bs[16 * 64];
    const int m0 = blockIdx.y * 64;
    const int o0 = blockIdx.x * 64;
    const int b  = m0 >> 10;
    const int n0 = m0 & 1023;
    const int tid = threadIdx.x;
    const int tr = tid >> 4, tc = tid & 15;
    const float* xb = x + (size_t)b * CH * NT;

    float acc[4][4] = {};
    for (int k0 = 0; k0 < CH; k0 += 16) {
        #pragma unroll
        for (int i = 0; i < 4; ++i) {
            int e  = tid + 256 * i;
            int kk = e >> 6, mm = e & 63;
            As[kk * 64 + mm] = xb[(size_t)(k0 + kk) * NT + n0 + mm];
            Bs[kk * 64 + mm] = Wp[(size_t)(k0 + kk) * QKV + o0 + mm];
        }
        __syncthreads();
        #pragma unroll
        for (int kk = 0; kk < 16; ++kk) {
            float4 a  = *(const float4*)(As + kk * 64 + tr * 4);
            float4 bv = *(const float4*)(Bs + kk * 64 + tc * 4);
            float ar[4] = {a.x, a.y, a.z, a.w};
            float br[4] = {bv.x, bv.y, bv.z, bv.w};
            #pragma unroll
            for (int i = 0; i < 4; ++i)
                #pragma unroll
                for (int j = 0; j < 4; ++j)
                    acc[i][j] += ar[i] * br[j];
        }
        __syncthreads();
    }

    // o0 = blockIdx.x*64 : head = bx/3, type = bx%3 (q,k,v), d = tc*4+j
    const int h = blockIdx.x / 3;
    const int t = blockIdx.x - 3 * h;
    float* dst = (t == 0) ? g_q : (t == 1) ? g_k : g_v;
    dst += (size_t)(b * NH + h) * NT * HD;
    float4 bias = *(const float4*)(bp + o0 + tc * 4);
    float br2[4] = {bias.x, bias.y, bias.z, bias.w};
    #pragma unroll
    for (int i = 0; i < 4; ++i) {
        int n = n0 + tr * 4 + i;
        float4 val;
        val.x = acc[i][0] + br2[0];
        val.y = acc[i][1] + br2[1];
        val.z = acc[i][2] + br2[2];
        val.w = acc[i][3] + br2[3];
        *(float4*)(dst + (size_t)n * HD + tc * 4) = val;
    }
}

// ---------------------------------------------------------------------------
// Kernel 2: S[bh, i, j] = scale * sum_d Q[bh,i,d] * K[bh,j,d]
// Both operands transpose-loaded into [kk][row] tiles (pad 68 -> float4-aligned
// conflict-free compute reads, 2-way conflict on stores only).
// ---------------------------------------------------------------------------
__global__ void __launch_bounds__(256) qk_gemm_kernel()
{
    __shared__ float As[16 * 68];
    __shared__ float Bs[16 * 68];
    const int bh = blockIdx.z;
    const int i0 = blockIdx.y * 64;
    const int j0 = blockIdx.x * 64;
    const float* Q = g_q + (size_t)bh * NT * HD;
    const float* K = g_k + (size_t)bh * NT * HD;
    const int tid = threadIdx.x;
    const int tr = tid >> 4, tc = tid & 15;

    float acc[4][4] = {};
    for (int k0 = 0; k0 < HD; k0 += 16) {
        #pragma unroll
        for (int i = 0; i < 4; ++i) {
            int e  = tid + 256 * i;
            int kk = e & 15, rr = e >> 4;
            As[kk * 68 + rr] = Q[(size_t)(i0 + rr) * HD + k0 + kk];
            Bs[kk * 68 + rr] = K[(size_t)(j0 + rr) * HD + k0 + kk];
        }
        __syncthreads();
        #pragma unroll
        for (int kk = 0; kk < 16; ++kk) {
            float4 a  = *(const float4*)(As + kk * 68 + tr * 4);
            float4 bv = *(const float4*)(Bs + kk * 68 + tc * 4);
            float ar[4] = {a.x, a.y, a.z, a.w};
            float br[4] = {bv.x, bv.y, bv.z, bv.w};
            #pragma unroll
            for (int i = 0; i < 4; ++i)
                #pragma unroll
                for (int j = 0; j < 4; ++j)
                    acc[i][j] += ar[i] * br[j];
        }
        __syncthreads();
    }

    float* Sp = g_S + (size_t)bh * NT * NT;
    const float scale = 0.125f;  // 64^-0.5
    #pragma unroll
    for (int i = 0; i < 4; ++i) {
        float4 val;
        val.x = acc[i][0] * scale;
        val.y = acc[i][1] * scale;
        val.z = acc[i][2] * scale;
        val.w = acc[i][3] * scale;
        *(float4*)(Sp + (size_t)(i0 + tr * 4 + i) * NT + j0 + tc * 4) = val;
    }
}

// ---------------------------------------------------------------------------
// Kernel 3: row softmax over j (1024). One warp per row; row lives in 8
// float4 registers per lane -> single gmem read + single write.
// ---------------------------------------------------------------------------
__global__ void __launch_bounds__(256) softmax_kernel()
{
    const size_t row = (size_t)blockIdx.x * 8 + (threadIdx.x >> 5);
    const int lane = threadIdx.x & 31;
    float4* p = (float4*)(g_S + row * NT) + lane;

    float4 v[8];
    float mx = -1e30f;
    #pragma unroll
    for (int t = 0; t < 8; ++t) {
        v[t] = p[(size_t)t * 32];
        mx = fmaxf(mx, fmaxf(fmaxf(v[t].x, v[t].y), fmaxf(v[t].z, v[t].w)));
    }
    #pragma unroll
    for (int off = 16; off; off >>= 1)
        mx = fmaxf(mx, __shfl_xor_sync(0xffffffffu, mx, off));

    float s = 0.f;
    #pragma unroll
    for (int t = 0; t < 8; ++t) {
        v[t].x = __expf(v[t].x - mx);
        v[t].y = __expf(v[t].y - mx);
        v[t].z = __expf(v[t].z - mx);
        v[t].w = __expf(v[t].w - mx);
        s += v[t].x + v[t].y + v[t].z + v[t].w;
    }
    #pragma unroll
    for (int off = 16; off; off >>= 1)
        s += __shfl_xor_sync(0xffffffffu, s, off);

    const float inv = 1.f / s;
    #pragma unroll
    for (int t = 0; t < 8; ++t) {
        v[t].x *= inv; v[t].y *= inv; v[t].z *= inv; v[t].w *= inv;
        p[(size_t)t * 32] = v[t];
    }
}

// ---------------------------------------------------------------------------
// Kernel 4: O[bh, i, d] = sum_j P[bh,i,j] * V[bh,j,d]; writes to g_ao[b][n][h*64+d]
// ---------------------------------------------------------------------------
__global__ void __launch_bounds__(256) pv_gemm_kernel()
{
    __shared__ float As[16 * 68];
    __shared__ float Bs[16 * 68];
    const int bh = blockIdx.z;
    const int i0 = blockIdx.y * 64;
    const float* P = g_S + (size_t)bh * NT * NT;
    const float* V = g_v + (size_t)bh * NT * HD;
    const int tid = threadIdx.x;
    const int tr = tid >> 4, tc = tid & 15;

    float acc[4][4] = {};
    for (int k0 = 0; k0 < NT; k0 += 16) {
        #pragma unroll
        for (int i = 0; i < 4; ++i) {
            int e = tid + 256 * i;
            {   // P transposed load: As[kk][ii]
                int kk = e & 15, rr = e >> 4;
                As[kk * 68 + rr] = P[(size_t)(i0 + rr) * NT + k0 + kk];
            }
            {   // V straight load: Bs[kk][dd]
                int kk = e >> 6, dd = e & 63;
                Bs[kk * 68 + dd] = V[(size_t)(k0 + kk) * HD + dd];
            }
        }
        __syncthreads();
        #pragma unroll
        for (int kk = 0; kk < 16; ++kk) {
            float4 a  = *(const float4*)(As + kk * 68 + tr * 4);
            float4 bv = *(const float4*)(Bs + kk * 68 + tc * 4);
            float ar[4] = {a.x, a.y, a.z, a.w};
            float br[4] = {bv.x, bv.y, bv.z, bv.w};
            #pragma unroll
            for (int i = 0; i < 4; ++i)
                #pragma unroll
                for (int j = 0; j < 4; ++j)
                    acc[i][j] += ar[i] * br[j];
        }
        __syncthreads();
    }

    const int b = bh >> 2, h = bh & 3;
    float* ao = g_ao + (size_t)b * NT * CH + h * HD;
    #pragma unroll
    for (int i = 0; i < 4; ++i) {
        float4 val;
        val.x = acc[i][0]; val.y = acc[i][1]; val.z = acc[i][2]; val.w = acc[i][3];
        *(float4*)(ao + (size_t)(i0 + tr * 4 + i) * CH + tc * 4) = val;
    }
}

// ---------------------------------------------------------------------------
// Kernel 5: out[b, c, n] = sum_k g_ao[b,n,k] * Wo[k,c] + bo[c] + x[b,c,n]
// ---------------------------------------------------------------------------
__global__ void __launch_bounds__(256) out_proj_kernel(
    const float* __restrict__ x, const float* __restrict__ Wo,
    const float* __restrict__ bo, float* __restrict__ out)
{
    __shared__ float As[16 * 68];
    __shared__ float Bs[16 * 68];
    const int m0 = blockIdx.y * 64;        // m = b*1024 + n
    const int c0 = blockIdx.x * 64;
    const int b  = m0 >> 10;
    const int n0 = m0 & 1023;
    const int tid = threadIdx.x;
    const int tr = tid >> 4, tc = tid & 15;

    float acc[4][4] = {};
    for (int k0 = 0; k0 < CH; k0 += 16) {
        #pragma unroll
        for (int i = 0; i < 4; ++i) {
            int e = tid + 256 * i;
            {   // g_ao transposed load
                int kk = e & 15, mm = e >> 4;
                As[kk * 68 + mm] = g_ao[(size_t)(m0 + mm) * CH + k0 + kk];
            }
            {   // Wo straight load
                int kk = e >> 6, cc = e & 63;
                Bs[kk * 68 + cc] = Wo[(size_t)(k0 + kk) * CH + c0 + cc];
            }
        }
        __syncthreads();
        #pragma unroll
        for (int kk = 0; kk < 16; ++kk) {
            float4 a  = *(const float4*)(As + kk * 68 + tr * 4);
            float4 bv = *(const float4*)(Bs + kk * 68 + tc * 4);
            float ar[4] = {a.x, a.y, a.z, a.w};
            float br[4] = {bv.x, bv.y, bv.z, bv.w};
            #pragma unroll
            for (int i = 0; i < 4; ++i)
                #pragma unroll
                for (int j = 0; j < 4; ++j)
                    acc[i][j] += ar[i] * br[j];
        }
        __syncthreads();
    }

    const float* xb = x   + (size_t)b * CH * NT;
    float*       ob = out + (size_t)b * CH * NT;
    #pragma unroll
    for (int j = 0; j < 4; ++j) {
        int c = c0 + tc * 4 + j;
        int n = n0 + tr * 4;
        float bias = bo[c];
        float4 xr = *(const float4*)(xb + (size_t)c * NT + n);
        float4 val;
        val.x = acc[0][j] + bias + xr.x;
        val.y = acc[1][j] + bias + xr.y;
        val.z = acc[2][j] + bias + xr.z;
        val.w = acc[3][j] + bias + xr.w;
        *(float4*)(ob + (size_t)c * NT + n) = val;
    }
}

// ---------------------------------------------------------------------------
extern "C" void kernel_launch(void* const* d_in, const int* in_sizes, int n_in,
                              void* d_out, int out_size)
{
    const float* x  = (const float*)d_in[0];
    const float* Wp = (const float*)d_in[1];
    const float* bp = (const float*)d_in[2];
    const float* Wo = (const float*)d_in[3];
    const float* bo = (const float*)d_in[4];
    float* out = (float*)d_out;

    // 1) QKV projection:  grid (768/64, 8192/64)
    qkv_proj_kernel<<<dim3(QKV / 64, (BATCH * NT) / 64), 256>>>(x, Wp, bp);
    // 2) S = scale * Q K^T per (b,h):  grid (16, 16, 32)
    qk_gemm_kernel<<<dim3(NT / 64, NT / 64, BATCH * NH), 256>>>();
    // 3) softmax rows (32768 rows, 8 per block)
    softmax_kernel<<<(BATCH * NH * NT) / 8, 256>>>();
    // 4) O = P V:  grid (1, 16, 32)
    pv_gemm_kernel<<<dim3(1, NT / 64, BATCH * NH), 256>>>();
    // 5) output projection + bias + residual + NCHW transpose
    out_proj_kernel<<<dim3(CH / 64, (BATCH * NT) / 64), 256>>>(x, Wo, bo, out);
}